// round 15
// baseline (speedup 1.0000x reference)
#include <cuda_runtime.h>
#include <cuda_fp16.h>
#include <cstdint>

#define N_NODESC 100000
#define N_EDGESC 2500000
#define IN_CH 32
#define HID 16
#define OUT_CH 64
#define NUM_GRAPHS 64

// ---------------- scratch ----------------
__device__ __align__(32) __half2 g_yh[N_NODESC * 8];     // f16(x @ w1_l^T)
__device__ __align__(32) __half2 g_h1h[N_NODESC * 8];    // f16(h1)
__device__ __align__(32) __half2 g_agg1h[N_NODESC * 8];  // zero steady-state
__device__ __align__(32) __half2 g_agg2h[N_NODESC * 8];  // zero steady-state
__device__ __align__(16) float g_xr[N_NODESC * HID];
__device__ __align__(16) float g_cnt[N_NODESC];          // zero steady-state (re-zeroed by kMean2R)
__device__ __align__(16) float g_h1acc[NUM_GRAPHS * HID];
__device__ __align__(16) float g_m2acc[NUM_GRAPHS * HID];
__device__ __align__(16) float g_gcnt[NUM_GRAPHS];

__device__ __forceinline__ void red_add_v4f(float* p, float a, float b, float c, float d) {
    asm volatile("red.global.add.v4.f32 [%0], {%1, %2, %3, %4};"
                 :: "l"(p), "f"(a), "f"(b), "f"(c), "f"(d) : "memory");
}
__device__ __forceinline__ void red_add_v4h(__half2* p, uint4 v) {
    asm volatile("red.global.add.noftz.v4.f16x2 [%0], {%1, %2, %3, %4};"
                 :: "l"(p), "r"(v.x), "r"(v.y), "r"(v.z), "r"(v.w) : "memory");
}

// ---------------- Kernel 0 (side stream): degree count ----------------
__global__ void __launch_bounds__(256) kDeg(const int* __restrict__ ei) {
    int t = blockIdx.x * blockDim.x + threadIdx.x;
    if (t >= N_EDGESC / 4) return;
    int4 dd = __ldg(reinterpret_cast<const int4*>(ei + N_EDGESC) + t);
    atomicAdd(&g_cnt[dd.x], 1.0f);
    atomicAdd(&g_cnt[dd.y], 1.0f);
    atomicAdd(&g_cnt[dd.z], 1.0f);
    atomicAdd(&g_cnt[dd.w], 1.0f);
}

// ---------------- Kernel 1: pre-transform; zero small accumulators ----------------
// NOTE: must NOT touch g_cnt (runs concurrently with kDeg on the forked stream).
__global__ void __launch_bounds__(256) kPre(const float* __restrict__ x,
                                            const float* __restrict__ w1l,
                                            const float* __restrict__ w1r) {
    __shared__ __align__(16) float swl[HID * IN_CH];
    __shared__ __align__(16) float swr[HID * IN_CH];
    int t = threadIdx.x;
    for (int i = t; i < HID * IN_CH; i += blockDim.x) {
        swl[i] = w1l[i];
        swr[i] = w1r[i];
    }
    __syncthreads();

    int n = blockIdx.x * blockDim.x + t;
    if (n < N_NODESC) {
        if (n < NUM_GRAPHS * HID) { g_h1acc[n] = 0.0f; g_m2acc[n] = 0.0f; }
        if (n < NUM_GRAPHS) g_gcnt[n] = 0.0f;

        float xv[IN_CH];
        const float4* xp = reinterpret_cast<const float4*>(x + (size_t)n * IN_CH);
#pragma unroll
        for (int i = 0; i < IN_CH / 4; i++) {
            float4 v = __ldg(xp + i);
            xv[4*i+0] = v.x; xv[4*i+1] = v.y; xv[4*i+2] = v.z; xv[4*i+3] = v.w;
        }

        float yl[HID], yr[HID];
#pragma unroll
        for (int o = 0; o < HID; o++) {
            float al = 0.0f, ar = 0.0f;
#pragma unroll
            for (int kk = 0; kk < IN_CH / 4; kk++) {
                float4 wl = *reinterpret_cast<float4*>(&swl[o * IN_CH + kk * 4]);
                float4 wr = *reinterpret_cast<float4*>(&swr[o * IN_CH + kk * 4]);
                al += xv[kk*4+0]*wl.x + xv[kk*4+1]*wl.y + xv[kk*4+2]*wl.z + xv[kk*4+3]*wl.w;
                ar += xv[kk*4+0]*wr.x + xv[kk*4+1]*wr.y + xv[kk*4+2]*wr.z + xv[kk*4+3]*wr.w;
            }
            yl[o] = al; yr[o] = ar;
        }

        uint32_t yw[8];
#pragma unroll
        for (int i = 0; i < 8; i++) {
            __half2 h2 = __floats2half2_rn(yl[2*i], yl[2*i+1]);
            yw[i] = *reinterpret_cast<uint32_t*>(&h2);
        }
        uint4* yp = reinterpret_cast<uint4*>(g_yh + (size_t)n * 8);
        yp[0] = make_uint4(yw[0], yw[1], yw[2], yw[3]);
        yp[1] = make_uint4(yw[4], yw[5], yw[6], yw[7]);

        float4* rp = reinterpret_cast<float4*>(g_xr + (size_t)n * HID);
#pragma unroll
        for (int i = 0; i < HID / 4; i++)
            rp[i] = make_float4(yr[4*i], yr[4*i+1], yr[4*i+2], yr[4*i+3]);
    }
    cudaTriggerProgrammaticLaunchCompletion();
}

// ---------------- Kernel 2/4: f16 scatter, 4 edges per thread-pair, PDL ----------------
__global__ void __launch_bounds__(256) kScatterH(const int* __restrict__ ei,
                                                 const __half2* __restrict__ val,
                                                 __half2* __restrict__ acc) {
    int idx = blockIdx.x * blockDim.x + threadIdx.x;
    bool act = idx < N_EDGESC / 2;
    int p = idx >> 1;
    int c = idx & 1;

    // input-only prologue: edge indices
    int4 ss = make_int4(0,0,0,0), dd = make_int4(0,0,0,0);
    if (act) {
        ss = __ldg(reinterpret_cast<const int4*>(ei) + p);
        dd = __ldg(reinterpret_cast<const int4*>(ei + N_EDGESC) + p);
    }

    cudaGridDependencySynchronize();     // upstream writes (val, acc invariant) visible

    if (act) {
        uint4 v0 = __ldg(reinterpret_cast<const uint4*>(val) + (size_t)ss.x * 2 + c);
        uint4 v1 = __ldg(reinterpret_cast<const uint4*>(val) + (size_t)ss.y * 2 + c);
        uint4 v2 = __ldg(reinterpret_cast<const uint4*>(val) + (size_t)ss.z * 2 + c);
        uint4 v3 = __ldg(reinterpret_cast<const uint4*>(val) + (size_t)ss.w * 2 + c);
        red_add_v4h(acc + (size_t)dd.x * 8 + c * 4, v0);
        red_add_v4h(acc + (size_t)dd.y * 8 + c * 4, v1);
        red_add_v4h(acc + (size_t)dd.z * 8 + c * 4, v2);
        red_add_v4h(acc + (size_t)dd.w * 8 + c * 4, v3);
    }
    cudaTriggerProgrammaticLaunchCompletion();
}

// ---------------- Kernel 3: h1 = relu(mean(agg1)+b1+xr); re-zero agg1; readout; PDL ----------------
__global__ void __launch_bounds__(256) kLayer1R(const float* __restrict__ b1,
                                                const int* __restrict__ batch) {
    int n = blockIdx.x * blockDim.x + threadIdx.x;
    bool valid = n < N_NODESC;
    int nn = valid ? n : (N_NODESC - 1);
    int lane = threadIdx.x & 31;

    // input-only prologue
    int g = __ldg(&batch[nn]);
    float4 bb0 = __ldg(reinterpret_cast<const float4*>(b1) + 0);
    float4 bb1 = __ldg(reinterpret_cast<const float4*>(b1) + 1);
    float4 bb2 = __ldg(reinterpret_cast<const float4*>(b1) + 2);
    float4 bb3 = __ldg(reinterpret_cast<const float4*>(b1) + 3);

    cudaGridDependencySynchronize();   // agg1 (scatter-1) + cnt (kDeg via event join) visible

    float inv = 1.0f / fmaxf(g_cnt[nn], 1.0f);
    uint4* ap = reinterpret_cast<uint4*>(g_agg1h + (size_t)nn * 8);
    uint4 a0 = ap[0], a1 = ap[1];
    uint32_t aw[8] = {a0.x, a0.y, a0.z, a0.w, a1.x, a1.y, a1.z, a1.w};

    float h[HID];
#pragma unroll
    for (int i = 0; i < 8; i++) {
        __half2 h2 = *reinterpret_cast<__half2*>(&aw[i]);
        float2 f = __half22float2(h2);
        h[2*i]   = f.x * inv;
        h[2*i+1] = f.y * inv;
    }
    const float4* rp = reinterpret_cast<const float4*>(g_xr + (size_t)nn * HID);
    float4 bbs[4] = {bb0, bb1, bb2, bb3};
#pragma unroll
    for (int i = 0; i < 4; i++) {
        float4 r = rp[i];
        h[4*i+0] = fmaxf(h[4*i+0] + bbs[i].x + r.x, 0.0f);
        h[4*i+1] = fmaxf(h[4*i+1] + bbs[i].y + r.y, 0.0f);
        h[4*i+2] = fmaxf(h[4*i+2] + bbs[i].z + r.z, 0.0f);
        h[4*i+3] = fmaxf(h[4*i+3] + bbs[i].w + r.w, 0.0f);
    }

    if (valid) {
        uint32_t hw[8];
#pragma unroll
        for (int i = 0; i < 8; i++) {
            __half2 h2 = __floats2half2_rn(h[2*i], h[2*i+1]);
            hw[i] = *reinterpret_cast<uint32_t*>(&h2);
        }
        uint4* hp = reinterpret_cast<uint4*>(g_h1h + (size_t)n * 8);
        hp[0] = make_uint4(hw[0], hw[1], hw[2], hw[3]);
        hp[1] = make_uint4(hw[4], hw[5], hw[6], hw[7]);
        ap[0] = make_uint4(0, 0, 0, 0);       // re-zero agg1 (invariant)
        ap[1] = make_uint4(0, 0, 0, 0);
    } else {
#pragma unroll
        for (int o = 0; o < HID; o++) h[o] = 0.0f;
    }

    int g0 = __shfl_sync(0xffffffffu, g, 0);
    bool uni = __all_sync(0xffffffffu, g == g0);
    int nval = __popc(__ballot_sync(0xffffffffu, valid));

    if (uni) {
#pragma unroll
        for (int k = 0; k < HID; k++) {
            float v = h[k];
            v += __shfl_xor_sync(0xffffffffu, v, 16);
            v += __shfl_xor_sync(0xffffffffu, v, 8);
            v += __shfl_xor_sync(0xffffffffu, v, 4);
            v += __shfl_xor_sync(0xffffffffu, v, 2);
            v += __shfl_xor_sync(0xffffffffu, v, 1);
            h[k] = v;
        }
        if (lane == 0) {
            float* gp = g_h1acc + (size_t)g0 * HID;
#pragma unroll
            for (int k = 0; k < HID; k += 4)
                red_add_v4f(gp + k, h[k], h[k+1], h[k+2], h[k+3]);
            if (nval > 0) atomicAdd(&g_gcnt[g0], (float)nval);
        }
    } else if (valid) {
        float* gp = g_h1acc + (size_t)g * HID;
#pragma unroll
        for (int k = 0; k < HID; k += 4)
            red_add_v4f(gp + k, h[k], h[k+1], h[k+2], h[k+3]);
        atomicAdd(&g_gcnt[g], 1.0f);
    }
    cudaTriggerProgrammaticLaunchCompletion();
}

// ---------------- Kernel 5: m2 = mean(agg2); re-zero agg2 + cnt; readout; PDL ----------------
__global__ void __launch_bounds__(256) kMean2R(const int* __restrict__ batch) {
    int n = blockIdx.x * blockDim.x + threadIdx.x;
    bool valid = n < N_NODESC;
    int nn = valid ? n : (N_NODESC - 1);
    int lane = threadIdx.x & 31;

    int g = __ldg(&batch[nn]);          // input-only prologue

    cudaGridDependencySynchronize();    // agg2/cnt now visible

    float inv = 1.0f / fmaxf(g_cnt[nn], 1.0f);
    uint4* ap = reinterpret_cast<uint4*>(g_agg2h + (size_t)nn * 8);
    uint4 a0 = ap[0], a1 = ap[1];
    uint32_t aw[8] = {a0.x, a0.y, a0.z, a0.w, a1.x, a1.y, a1.z, a1.w};

    if (valid) {
        ap[0] = make_uint4(0, 0, 0, 0);       // re-zero agg2 (invariant)
        ap[1] = make_uint4(0, 0, 0, 0);
        g_cnt[n] = 0.0f;                      // re-zero cnt (invariant; after last read)
    }

    float m[HID];
#pragma unroll
    for (int i = 0; i < 8; i++) {
        __half2 h2 = *reinterpret_cast<__half2*>(&aw[i]);
        float2 f = __half22float2(h2);
        m[2*i]   = valid ? f.x * inv : 0.0f;
        m[2*i+1] = valid ? f.y * inv : 0.0f;
    }

    int g0 = __shfl_sync(0xffffffffu, g, 0);
    bool uni = __all_sync(0xffffffffu, g == g0);

    if (uni) {
#pragma unroll
        for (int k = 0; k < HID; k++) {
            float v = m[k];
            v += __shfl_xor_sync(0xffffffffu, v, 16);
            v += __shfl_xor_sync(0xffffffffu, v, 8);
            v += __shfl_xor_sync(0xffffffffu, v, 4);
            v += __shfl_xor_sync(0xffffffffu, v, 2);
            v += __shfl_xor_sync(0xffffffffu, v, 1);
            m[k] = v;
        }
        if (lane == 0) {
            float* gp = g_m2acc + (size_t)g0 * HID;
#pragma unroll
            for (int k = 0; k < HID; k += 4)
                red_add_v4f(gp + k, m[k], m[k+1], m[k+2], m[k+3]);
        }
    } else if (valid) {
        float* gp = g_m2acc + (size_t)g * HID;
#pragma unroll
        for (int k = 0; k < HID; k += 4)
            red_add_v4f(gp + k, m[k], m[k+1], m[k+2], m[k+3]);
    }
    cudaTriggerProgrammaticLaunchCompletion();
}

// ---------------- Kernel 6: tiny output GEMM; PDL ----------------
__global__ void __launch_bounds__(256) kFinal(const float* __restrict__ w2l,
                                              const float* __restrict__ b2,
                                              const float* __restrict__ w2r,
                                              float* __restrict__ out) {
    int i = blockIdx.x * blockDim.x + threadIdx.x;
    bool act = i < NUM_GRAPHS * OUT_CH;
    int g = i >> 6;
    int o = i & 63;

    float bias = 0.0f;
    float4 wl[4], wr[4];
    if (act) {
        bias = __ldg(&b2[o]);
#pragma unroll
        for (int k = 0; k < 4; k++) {
            wl[k] = __ldg(reinterpret_cast<const float4*>(w2l + o * HID + k * 4));
            wr[k] = __ldg(reinterpret_cast<const float4*>(w2r + o * HID + k * 4));
        }
    }

    cudaGridDependencySynchronize();    // gacc/gcnt now visible

    if (!act) return;
    float cnt = g_gcnt[g];
    if (cnt < 0.5f) { out[i] = 0.0f; return; }
    float inv = 1.0f / cnt;

    float sum = bias;
#pragma unroll
    for (int k = 0; k < 4; k++) {
        float4 mm = *reinterpret_cast<const float4*>(&g_m2acc[g * HID + k * 4]);
        float4 hh = *reinterpret_cast<const float4*>(&g_h1acc[g * HID + k * 4]);
        sum += inv * (mm.x * wl[k].x + mm.y * wl[k].y + mm.z * wl[k].z + mm.w * wl[k].w
                    + hh.x * wr[k].x + hh.y * wr[k].y + hh.z * wr[k].z + hh.w * wr[k].w);
    }
    out[i] = sum;
}

// ---------------- launch ----------------
template <typename K, typename... Args>
static void launchPDL(int grid, int block, K kernel, Args... args) {
    cudaLaunchConfig_t cfg = {};
    cfg.gridDim = dim3(grid);
    cfg.blockDim = dim3(block);
    cfg.stream = 0;
    cudaLaunchAttribute attr[1];
    attr[0].id = cudaLaunchAttributeProgrammaticStreamSerialization;
    attr[0].val.programmaticStreamSerializationAllowed = 1;
    cfg.attrs = attr;
    cfg.numAttrs = 1;
    cudaLaunchKernelEx(&cfg, kernel, args...);
}

extern "C" void kernel_launch(void* const* d_in, const int* in_sizes, int n_in,
                              void* d_out, int out_size) {
    const float* x    = (const float*)d_in[0];
    const int*   ei   = (const int*)d_in[1];
    const int*   batch= (const int*)d_in[2];
    const float* w1l  = (const float*)d_in[3];
    const float* b1   = (const float*)d_in[4];
    const float* w1r  = (const float*)d_in[5];
    const float* w2l  = (const float*)d_in[6];
    const float* b2   = (const float*)d_in[7];
    const float* w2r  = (const float*)d_in[8];
    float* out = (float*)d_out;

    __half2* gy;  cudaGetSymbolAddress((void**)&gy,  g_yh);
    __half2* gh1; cudaGetSymbolAddress((void**)&gh1, g_h1h);
    __half2* ga1; cudaGetSymbolAddress((void**)&ga1, g_agg1h);
    __half2* ga2; cudaGetSymbolAddress((void**)&ga2, g_agg2h);

    const int TB = 256;
    int nodeBlocks = (N_NODESC + TB - 1) / TB;
    int scatBlocks = (N_EDGESC / 2 + TB - 1) / TB;   // 4 edges / thread-pair
    int degBlocks  = (N_EDGESC / 4 + TB - 1) / TB;   // 4 edges / thread

    // fork: degree count on a side stream, concurrent with kPre + scatter-1
    cudaStream_t s2;
    cudaStreamCreateWithFlags(&s2, cudaStreamNonBlocking);
    cudaEvent_t evFork, evJoin;
    cudaEventCreateWithFlags(&evFork, cudaEventDisableTiming);
    cudaEventCreateWithFlags(&evJoin, cudaEventDisableTiming);

    cudaEventRecord(evFork, 0);
    cudaStreamWaitEvent(s2, evFork, 0);
    kDeg<<<degBlocks, TB, 0, s2>>>(ei);
    cudaEventRecord(evJoin, s2);

    kPre<<<nodeBlocks, TB>>>(x, w1l, w1r);
    launchPDL(scatBlocks, TB, kScatterH, ei, (const __half2*)gy, ga1);
    cudaStreamWaitEvent(0, evJoin, 0);               // counts ready before first reader
    launchPDL(nodeBlocks, TB, kLayer1R, b1, batch);
    launchPDL(scatBlocks, TB, kScatterH, ei, (const __half2*)gh1, ga2);
    launchPDL(nodeBlocks, TB, kMean2R, batch);
    launchPDL((NUM_GRAPHS * OUT_CH + TB - 1) / TB, TB, kFinal, w2l, b2, w2r, out);
}

// round 16
// speedup vs baseline: 1.0903x; 1.0903x over previous
#include <cuda_runtime.h>
#include <cuda_fp16.h>
#include <cstdint>

#define N_NODESC 100000
#define N_EDGESC 2500000
#define IN_CH 32
#define HID 16
#define OUT_CH 64
#define NUM_GRAPHS 64

// ---------------- scratch ----------------
__device__ __align__(32) __half2 g_yh[N_NODESC * 8];     // f16(x @ w1_l^T)
__device__ __align__(32) __half2 g_h1h[N_NODESC * 8];    // f16(h1)
__device__ __align__(32) __half2 g_agg1h[N_NODESC * 8];  // zero steady-state
__device__ __align__(32) __half2 g_agg2h[N_NODESC * 8];  // zero steady-state
__device__ __align__(16) float g_xr[N_NODESC * HID];
__device__ __align__(16) float g_cnt[N_NODESC];          // zero steady-state (re-zeroed by kMean2R)
__device__ __align__(16) float g_h1acc[NUM_GRAPHS * HID];
__device__ __align__(16) float g_m2acc[NUM_GRAPHS * HID];
__device__ __align__(16) float g_gcnt[NUM_GRAPHS];

__device__ __forceinline__ void red_add_v4f(float* p, float a, float b, float c, float d) {
    asm volatile("red.global.add.v4.f32 [%0], {%1, %2, %3, %4};"
                 :: "l"(p), "f"(a), "f"(b), "f"(c), "f"(d) : "memory");
}
__device__ __forceinline__ void red_add_v4h(__half2* p, uint4 v) {
    asm volatile("red.global.add.noftz.v4.f16x2 [%0], {%1, %2, %3, %4};"
                 :: "l"(p), "r"(v.x), "r"(v.y), "r"(v.z), "r"(v.w) : "memory");
}

// ---------------- Kernel 1: pre-transform; zero small accumulators ----------------
__global__ void __launch_bounds__(256) kPre(const float* __restrict__ x,
                                            const float* __restrict__ w1l,
                                            const float* __restrict__ w1r) {
    __shared__ __align__(16) float swl[HID * IN_CH];
    __shared__ __align__(16) float swr[HID * IN_CH];
    int t = threadIdx.x;
    for (int i = t; i < HID * IN_CH; i += blockDim.x) {
        swl[i] = w1l[i];
        swr[i] = w1r[i];
    }
    __syncthreads();

    int n = blockIdx.x * blockDim.x + t;
    if (n < N_NODESC) {
        if (n < NUM_GRAPHS * HID) { g_h1acc[n] = 0.0f; g_m2acc[n] = 0.0f; }
        if (n < NUM_GRAPHS) g_gcnt[n] = 0.0f;

        float xv[IN_CH];
        const float4* xp = reinterpret_cast<const float4*>(x + (size_t)n * IN_CH);
#pragma unroll
        for (int i = 0; i < IN_CH / 4; i++) {
            float4 v = __ldg(xp + i);
            xv[4*i+0] = v.x; xv[4*i+1] = v.y; xv[4*i+2] = v.z; xv[4*i+3] = v.w;
        }

        float yl[HID], yr[HID];
#pragma unroll
        for (int o = 0; o < HID; o++) {
            float al = 0.0f, ar = 0.0f;
#pragma unroll
            for (int kk = 0; kk < IN_CH / 4; kk++) {
                float4 wl = *reinterpret_cast<float4*>(&swl[o * IN_CH + kk * 4]);
                float4 wr = *reinterpret_cast<float4*>(&swr[o * IN_CH + kk * 4]);
                al += xv[kk*4+0]*wl.x + xv[kk*4+1]*wl.y + xv[kk*4+2]*wl.z + xv[kk*4+3]*wl.w;
                ar += xv[kk*4+0]*wr.x + xv[kk*4+1]*wr.y + xv[kk*4+2]*wr.z + xv[kk*4+3]*wr.w;
            }
            yl[o] = al; yr[o] = ar;
        }

        uint32_t yw[8];
#pragma unroll
        for (int i = 0; i < 8; i++) {
            __half2 h2 = __floats2half2_rn(yl[2*i], yl[2*i+1]);
            yw[i] = *reinterpret_cast<uint32_t*>(&h2);
        }
        uint4* yp = reinterpret_cast<uint4*>(g_yh + (size_t)n * 8);
        yp[0] = make_uint4(yw[0], yw[1], yw[2], yw[3]);
        yp[1] = make_uint4(yw[4], yw[5], yw[6], yw[7]);

        float4* rp = reinterpret_cast<float4*>(g_xr + (size_t)n * HID);
#pragma unroll
        for (int i = 0; i < HID / 4; i++)
            rp[i] = make_float4(yr[4*i], yr[4*i+1], yr[4*i+2], yr[4*i+3]);
        // g_cnt zero by steady-state invariant (re-zeroed by kMean2R).
    }
    cudaTriggerProgrammaticLaunchCompletion();
}

// ---------------- Kernel 2/4: f16 scatter, 4 edges per thread-pair, PDL ----------------
// Round-13 wiring: counts (ADDCOUNT=1) in the post-sync body.
template <int ADDCOUNT>
__global__ void __launch_bounds__(256) kScatterH(const int* __restrict__ ei,
                                                 const __half2* __restrict__ val,
                                                 __half2* __restrict__ acc) {
    int idx = blockIdx.x * blockDim.x + threadIdx.x;
    bool act = idx < N_EDGESC / 2;
    int p = idx >> 1;
    int c = idx & 1;

    int4 ss = make_int4(0,0,0,0), dd = make_int4(0,0,0,0);
    if (act) {
        ss = __ldg(reinterpret_cast<const int4*>(ei) + p);
        dd = __ldg(reinterpret_cast<const int4*>(ei + N_EDGESC) + p);
    }

    cudaGridDependencySynchronize();

    if (act) {
        uint4 v0 = __ldg(reinterpret_cast<const uint4*>(val) + (size_t)ss.x * 2 + c);
        uint4 v1 = __ldg(reinterpret_cast<const uint4*>(val) + (size_t)ss.y * 2 + c);
        uint4 v2 = __ldg(reinterpret_cast<const uint4*>(val) + (size_t)ss.z * 2 + c);
        uint4 v3 = __ldg(reinterpret_cast<const uint4*>(val) + (size_t)ss.w * 2 + c);
        red_add_v4h(acc + (size_t)dd.x * 8 + c * 4, v0);
        red_add_v4h(acc + (size_t)dd.y * 8 + c * 4, v1);
        red_add_v4h(acc + (size_t)dd.z * 8 + c * 4, v2);
        red_add_v4h(acc + (size_t)dd.w * 8 + c * 4, v3);

        if (ADDCOUNT) {
            int da = c ? dd.z : dd.x;
            int db = c ? dd.w : dd.y;
            atomicAdd(&g_cnt[da], 1.0f);
            atomicAdd(&g_cnt[db], 1.0f);
        }
    }
    cudaTriggerProgrammaticLaunchCompletion();
}

// ---------------- Kernel 3: layer-1 epilogue + readout, 2 threads/node, PDL ----------------
__global__ void __launch_bounds__(256) kLayer1R(const float* __restrict__ b1,
                                                const int* __restrict__ batch) {
    int idx = blockIdx.x * blockDim.x + threadIdx.x;
    int n = idx >> 1;
    int c = idx & 1;                    // half-row: 8 channels
    bool valid = n < N_NODESC;
    int nn = valid ? n : (N_NODESC - 1);
    int lane = threadIdx.x & 31;

    // input-only prologue
    int g = __ldg(&batch[nn]);
    float4 bbA = __ldg(reinterpret_cast<const float4*>(b1) + c * 2);
    float4 bbB = __ldg(reinterpret_cast<const float4*>(b1) + c * 2 + 1);

    cudaGridDependencySynchronize();    // agg1/cnt/xr visible

    float inv = 1.0f / fmaxf(g_cnt[nn], 1.0f);
    uint4* ap = reinterpret_cast<uint4*>(g_agg1h + (size_t)nn * 8);
    uint4 a = ap[c];
    uint32_t aw[4] = {a.x, a.y, a.z, a.w};

    float h[8];
#pragma unroll
    for (int i = 0; i < 4; i++) {
        __half2 h2 = *reinterpret_cast<__half2*>(&aw[i]);
        float2 f = __half22float2(h2);
        h[2*i]   = f.x * inv;
        h[2*i+1] = f.y * inv;
    }
    const float4* rp = reinterpret_cast<const float4*>(g_xr + (size_t)nn * HID);
    float4 rA = rp[c * 2], rB = rp[c * 2 + 1];
    h[0] = fmaxf(h[0] + bbA.x + rA.x, 0.0f);
    h[1] = fmaxf(h[1] + bbA.y + rA.y, 0.0f);
    h[2] = fmaxf(h[2] + bbA.z + rA.z, 0.0f);
    h[3] = fmaxf(h[3] + bbA.w + rA.w, 0.0f);
    h[4] = fmaxf(h[4] + bbB.x + rB.x, 0.0f);
    h[5] = fmaxf(h[5] + bbB.y + rB.y, 0.0f);
    h[6] = fmaxf(h[6] + bbB.z + rB.z, 0.0f);
    h[7] = fmaxf(h[7] + bbB.w + rB.w, 0.0f);

    if (valid) {
        uint32_t hw[4];
#pragma unroll
        for (int i = 0; i < 4; i++) {
            __half2 h2 = __floats2half2_rn(h[2*i], h[2*i+1]);
            hw[i] = *reinterpret_cast<uint32_t*>(&h2);
        }
        reinterpret_cast<uint4*>(g_h1h + (size_t)n * 8)[c] = make_uint4(hw[0], hw[1], hw[2], hw[3]);
        ap[c] = make_uint4(0, 0, 0, 0);       // re-zero agg1 (invariant)
    } else {
#pragma unroll
        for (int o = 0; o < 8; o++) h[o] = 0.0f;
    }

    // ---- readout: reduce over the 16 nodes in this warp, preserving half-id c ----
    int g0 = __shfl_sync(0xffffffffu, g, 0);
    bool uni = __all_sync(0xffffffffu, g == g0);
    int nval = __popc(__ballot_sync(0xffffffffu, valid && c == 0));

    if (uni) {
#pragma unroll
        for (int k = 0; k < 8; k++) {
            float v = h[k];
            v += __shfl_xor_sync(0xffffffffu, v, 16);
            v += __shfl_xor_sync(0xffffffffu, v, 8);
            v += __shfl_xor_sync(0xffffffffu, v, 4);
            v += __shfl_xor_sync(0xffffffffu, v, 2);
            h[k] = v;
        }
        if (lane < 2) {                 // lane 0: c=0 half, lane 1: c=1 half
            float* gp = g_h1acc + (size_t)g0 * HID + lane * 8;
            red_add_v4f(gp + 0, h[0], h[1], h[2], h[3]);
            red_add_v4f(gp + 4, h[4], h[5], h[6], h[7]);
        }
        if (lane == 0 && nval > 0) atomicAdd(&g_gcnt[g0], (float)nval);
    } else if (valid) {
        float* gp = g_h1acc + (size_t)g * HID + c * 8;
        red_add_v4f(gp + 0, h[0], h[1], h[2], h[3]);
        red_add_v4f(gp + 4, h[4], h[5], h[6], h[7]);
        if (c == 0) atomicAdd(&g_gcnt[g], 1.0f);
    }
    cudaTriggerProgrammaticLaunchCompletion();
}

// ---------------- Kernel 5: m2 readout, 2 threads/node; re-zero agg2 + cnt; PDL ----------------
__global__ void __launch_bounds__(256) kMean2R(const int* __restrict__ batch) {
    int idx = blockIdx.x * blockDim.x + threadIdx.x;
    int n = idx >> 1;
    int c = idx & 1;
    bool valid = n < N_NODESC;
    int nn = valid ? n : (N_NODESC - 1);
    int lane = threadIdx.x & 31;

    int g = __ldg(&batch[nn]);          // input-only prologue

    cudaGridDependencySynchronize();    // agg2/cnt visible

    float inv = 1.0f / fmaxf(g_cnt[nn], 1.0f);
    uint4* ap = reinterpret_cast<uint4*>(g_agg2h + (size_t)nn * 8);
    uint4 a = ap[c];
    uint32_t aw[4] = {a.x, a.y, a.z, a.w};

    if (valid) {
        ap[c] = make_uint4(0, 0, 0, 0);       // re-zero agg2 (invariant)
        if (c == 0) g_cnt[n] = 0.0f;          // re-zero cnt (invariant; after last read)
    }

    float m[8];
#pragma unroll
    for (int i = 0; i < 4; i++) {
        __half2 h2 = *reinterpret_cast<__half2*>(&aw[i]);
        float2 f = __half22float2(h2);
        m[2*i]   = valid ? f.x * inv : 0.0f;
        m[2*i+1] = valid ? f.y * inv : 0.0f;
    }

    int g0 = __shfl_sync(0xffffffffu, g, 0);
    bool uni = __all_sync(0xffffffffu, g == g0);

    if (uni) {
#pragma unroll
        for (int k = 0; k < 8; k++) {
            float v = m[k];
            v += __shfl_xor_sync(0xffffffffu, v, 16);
            v += __shfl_xor_sync(0xffffffffu, v, 8);
            v += __shfl_xor_sync(0xffffffffu, v, 4);
            v += __shfl_xor_sync(0xffffffffu, v, 2);
            m[k] = v;
        }
        if (lane < 2) {
            float* gp = g_m2acc + (size_t)g0 * HID + lane * 8;
            red_add_v4f(gp + 0, m[0], m[1], m[2], m[3]);
            red_add_v4f(gp + 4, m[4], m[5], m[6], m[7]);
        }
    } else if (valid) {
        float* gp = g_m2acc + (size_t)g * HID + c * 8;
        red_add_v4f(gp + 0, m[0], m[1], m[2], m[3]);
        red_add_v4f(gp + 4, m[4], m[5], m[6], m[7]);
    }
    cudaTriggerProgrammaticLaunchCompletion();
}

// ---------------- Kernel 6: tiny output GEMM; PDL ----------------
__global__ void __launch_bounds__(256) kFinal(const float* __restrict__ w2l,
                                              const float* __restrict__ b2,
                                              const float* __restrict__ w2r,
                                              float* __restrict__ out) {
    int i = blockIdx.x * blockDim.x + threadIdx.x;
    bool act = i < NUM_GRAPHS * OUT_CH;
    int g = i >> 6;
    int o = i & 63;

    float bias = 0.0f;
    float4 wl[4], wr[4];
    if (act) {
        bias = __ldg(&b2[o]);
#pragma unroll
        for (int k = 0; k < 4; k++) {
            wl[k] = __ldg(reinterpret_cast<const float4*>(w2l + o * HID + k * 4));
            wr[k] = __ldg(reinterpret_cast<const float4*>(w2r + o * HID + k * 4));
        }
    }

    cudaGridDependencySynchronize();

    if (!act) return;
    float cnt = g_gcnt[g];
    if (cnt < 0.5f) { out[i] = 0.0f; return; }
    float inv = 1.0f / cnt;

    float sum = bias;
#pragma unroll
    for (int k = 0; k < 4; k++) {
        float4 mm = *reinterpret_cast<const float4*>(&g_m2acc[g * HID + k * 4]);
        float4 hh = *reinterpret_cast<const float4*>(&g_h1acc[g * HID + k * 4]);
        sum += inv * (mm.x * wl[k].x + mm.y * wl[k].y + mm.z * wl[k].z + mm.w * wl[k].w
                    + hh.x * wr[k].x + hh.y * wr[k].y + hh.z * wr[k].z + hh.w * wr[k].w);
    }
    out[i] = sum;
}

// ---------------- launch ----------------
template <typename K, typename... Args>
static void launchPDL(int grid, int block, K kernel, Args... args) {
    cudaLaunchConfig_t cfg = {};
    cfg.gridDim = dim3(grid);
    cfg.blockDim = dim3(block);
    cfg.stream = 0;
    cudaLaunchAttribute attr[1];
    attr[0].id = cudaLaunchAttributeProgrammaticStreamSerialization;
    attr[0].val.programmaticStreamSerializationAllowed = 1;
    cfg.attrs = attr;
    cfg.numAttrs = 1;
    cudaLaunchKernelEx(&cfg, kernel, args...);
}

extern "C" void kernel_launch(void* const* d_in, const int* in_sizes, int n_in,
                              void* d_out, int out_size) {
    const float* x    = (const float*)d_in[0];
    const int*   ei   = (const int*)d_in[1];
    const int*   batch= (const int*)d_in[2];
    const float* w1l  = (const float*)d_in[3];
    const float* b1   = (const float*)d_in[4];
    const float* w1r  = (const float*)d_in[5];
    const float* w2l  = (const float*)d_in[6];
    const float* b2   = (const float*)d_in[7];
    const float* w2r  = (const float*)d_in[8];
    float* out = (float*)d_out;

    __half2* gy;  cudaGetSymbolAddress((void**)&gy,  g_yh);
    __half2* gh1; cudaGetSymbolAddress((void**)&gh1, g_h1h);
    __half2* ga1; cudaGetSymbolAddress((void**)&ga1, g_agg1h);
    __half2* ga2; cudaGetSymbolAddress((void**)&ga2, g_agg2h);

    const int TB = 256;
    int nodeBlocks  = (N_NODESC + TB - 1) / TB;
    int node2Blocks = (N_NODESC * 2 + TB - 1) / TB;    // 2 threads/node
    int scatBlocks  = (N_EDGESC / 2 + TB - 1) / TB;    // 4 edges / thread-pair

    kPre<<<nodeBlocks, TB>>>(x, w1l, w1r);
    launchPDL(scatBlocks, TB, kScatterH<1>, ei, (const __half2*)gy, ga1);
    launchPDL(node2Blocks, TB, kLayer1R, b1, batch);
    launchPDL(scatBlocks, TB, kScatterH<0>, ei, (const __half2*)gh1, ga2);
    launchPDL(node2Blocks, TB, kMean2R, batch);
    launchPDL((NUM_GRAPHS * OUT_CH + TB - 1) / TB, TB, kFinal, w2l, b2, w2r, out);
}

// round 17
// speedup vs baseline: 1.1049x; 1.0134x over previous
#include <cuda_runtime.h>
#include <cuda_fp16.h>
#include <cstdint>

#define N_NODESC 100000
#define N_EDGESC 2500000
#define IN_CH 32
#define HID 16
#define OUT_CH 64
#define NUM_GRAPHS 64

// ---------------- scratch ----------------
__device__ __align__(32) __half2 g_yh[N_NODESC * 8];     // f16(x @ w1_l^T)
__device__ __align__(32) __half2 g_h1h[N_NODESC * 8];    // f16(h1)
__device__ __align__(32) __half2 g_xrh[N_NODESC * 8];    // f16(x @ w1_r^T)
__device__ __align__(32) __half2 g_agg1h[N_NODESC * 8];  // zero steady-state
__device__ __align__(32) __half2 g_agg2h[N_NODESC * 8];  // zero steady-state
__device__ __align__(16) float g_cnt[N_NODESC];          // zero steady-state (re-zeroed by kMean2R)
__device__ __align__(16) float g_h1acc[NUM_GRAPHS * HID];
__device__ __align__(16) float g_m2acc[NUM_GRAPHS * HID];
__device__ __align__(16) float g_gcnt[NUM_GRAPHS];

__device__ __forceinline__ void red_add_v4f(float* p, float a, float b, float c, float d) {
    asm volatile("red.global.add.v4.f32 [%0], {%1, %2, %3, %4};"
                 :: "l"(p), "f"(a), "f"(b), "f"(c), "f"(d) : "memory");
}
__device__ __forceinline__ void red_add_v4h(__half2* p, uint4 v) {
    asm volatile("red.global.add.noftz.v4.f16x2 [%0], {%1, %2, %3, %4};"
                 :: "l"(p), "r"(v.x), "r"(v.y), "r"(v.z), "r"(v.w) : "memory");
}

// ---------------- Kernel 1: pre-transform; zero small accumulators; EARLY trigger ----------------
__global__ void __launch_bounds__(256) kPre(const float* __restrict__ x,
                                            const float* __restrict__ w1l,
                                            const float* __restrict__ w1r) {
    __shared__ __align__(16) float swl[HID * IN_CH];
    __shared__ __align__(16) float swr[HID * IN_CH];
    int t = threadIdx.x;
    for (int i = t; i < HID * IN_CH; i += blockDim.x) {
        swl[i] = w1l[i];
        swr[i] = w1r[i];
    }
    __syncthreads();
    // EARLY trigger: scatter-1 may launch now and prefetch its 20MB of edge
    // indices while we do the GEMV. Its GridDependencySync still waits for
    // all of kPre's writes.
    cudaTriggerProgrammaticLaunchCompletion();

    int n = blockIdx.x * blockDim.x + t;
    if (n < N_NODESC) {
        if (n < NUM_GRAPHS * HID) { g_h1acc[n] = 0.0f; g_m2acc[n] = 0.0f; }
        if (n < NUM_GRAPHS) g_gcnt[n] = 0.0f;

        float xv[IN_CH];
        const float4* xp = reinterpret_cast<const float4*>(x + (size_t)n * IN_CH);
#pragma unroll
        for (int i = 0; i < IN_CH / 4; i++) {
            float4 v = __ldg(xp + i);
            xv[4*i+0] = v.x; xv[4*i+1] = v.y; xv[4*i+2] = v.z; xv[4*i+3] = v.w;
        }

        float yl[HID], yr[HID];
#pragma unroll
        for (int o = 0; o < HID; o++) {
            float al = 0.0f, ar = 0.0f;
#pragma unroll
            for (int kk = 0; kk < IN_CH / 4; kk++) {
                float4 wl = *reinterpret_cast<float4*>(&swl[o * IN_CH + kk * 4]);
                float4 wr = *reinterpret_cast<float4*>(&swr[o * IN_CH + kk * 4]);
                al += xv[kk*4+0]*wl.x + xv[kk*4+1]*wl.y + xv[kk*4+2]*wl.z + xv[kk*4+3]*wl.w;
                ar += xv[kk*4+0]*wr.x + xv[kk*4+1]*wr.y + xv[kk*4+2]*wr.z + xv[kk*4+3]*wr.w;
            }
            yl[o] = al; yr[o] = ar;
        }

        uint32_t yw[8], rw[8];
#pragma unroll
        for (int i = 0; i < 8; i++) {
            __half2 hy = __floats2half2_rn(yl[2*i], yl[2*i+1]);
            __half2 hr = __floats2half2_rn(yr[2*i], yr[2*i+1]);
            yw[i] = *reinterpret_cast<uint32_t*>(&hy);
            rw[i] = *reinterpret_cast<uint32_t*>(&hr);
        }
        uint4* yp = reinterpret_cast<uint4*>(g_yh + (size_t)n * 8);
        yp[0] = make_uint4(yw[0], yw[1], yw[2], yw[3]);
        yp[1] = make_uint4(yw[4], yw[5], yw[6], yw[7]);
        uint4* rp = reinterpret_cast<uint4*>(g_xrh + (size_t)n * 8);
        rp[0] = make_uint4(rw[0], rw[1], rw[2], rw[3]);
        rp[1] = make_uint4(rw[4], rw[5], rw[6], rw[7]);
        // g_cnt zero by steady-state invariant (re-zeroed by kMean2R).
    }
}

// ---------------- Kernel 2/4: f16 scatter, 4 edges per thread-pair, PDL (END trigger) ----------------
template <int ADDCOUNT>
__global__ void __launch_bounds__(256) kScatterH(const int* __restrict__ ei,
                                                 const __half2* __restrict__ val,
                                                 __half2* __restrict__ acc) {
    int idx = blockIdx.x * blockDim.x + threadIdx.x;
    bool act = idx < N_EDGESC / 2;
    int p = idx >> 1;
    int c = idx & 1;

    // prologue: index prefetch (overlaps upstream via its early trigger)
    int4 ss = make_int4(0,0,0,0), dd = make_int4(0,0,0,0);
    if (act) {
        ss = __ldg(reinterpret_cast<const int4*>(ei) + p);
        dd = __ldg(reinterpret_cast<const int4*>(ei + N_EDGESC) + p);
    }

    cudaGridDependencySynchronize();

    if (act) {
        uint4 v0 = __ldg(reinterpret_cast<const uint4*>(val) + (size_t)ss.x * 2 + c);
        uint4 v1 = __ldg(reinterpret_cast<const uint4*>(val) + (size_t)ss.y * 2 + c);
        uint4 v2 = __ldg(reinterpret_cast<const uint4*>(val) + (size_t)ss.z * 2 + c);
        uint4 v3 = __ldg(reinterpret_cast<const uint4*>(val) + (size_t)ss.w * 2 + c);
        red_add_v4h(acc + (size_t)dd.x * 8 + c * 4, v0);
        red_add_v4h(acc + (size_t)dd.y * 8 + c * 4, v1);
        red_add_v4h(acc + (size_t)dd.z * 8 + c * 4, v2);
        red_add_v4h(acc + (size_t)dd.w * 8 + c * 4, v3);

        if (ADDCOUNT) {
            int da = c ? dd.z : dd.x;
            int db = c ? dd.w : dd.y;
            atomicAdd(&g_cnt[da], 1.0f);
            atomicAdd(&g_cnt[db], 1.0f);
        }
    }
    cudaTriggerProgrammaticLaunchCompletion();   // end trigger: avoid contention with 30us body
}

// ---------------- Kernel 3: layer-1 epilogue + readout, 2 threads/node; EARLY trigger ----------------
__global__ void __launch_bounds__(256) kLayer1R(const float* __restrict__ b1,
                                                const int* __restrict__ batch) {
    int idx = blockIdx.x * blockDim.x + threadIdx.x;
    int n = idx >> 1;
    int c = idx & 1;                    // half-row: 8 channels
    bool valid = n < N_NODESC;
    int nn = valid ? n : (N_NODESC - 1);
    int lane = threadIdx.x & 31;

    // input-only prologue
    int g = __ldg(&batch[nn]);
    float4 bbA = __ldg(reinterpret_cast<const float4*>(b1) + c * 2);
    float4 bbB = __ldg(reinterpret_cast<const float4*>(b1) + c * 2 + 1);

    cudaGridDependencySynchronize();    // agg1/cnt/xr visible
    // EARLY trigger: scatter-2 launches now and prefetches its indices
    // during this kernel's ~5us body.
    cudaTriggerProgrammaticLaunchCompletion();

    float inv = 1.0f / fmaxf(g_cnt[nn], 1.0f);
    uint4* ap = reinterpret_cast<uint4*>(g_agg1h + (size_t)nn * 8);
    uint4 a = ap[c];
    uint32_t aw[4] = {a.x, a.y, a.z, a.w};
    uint4 xw = reinterpret_cast<const uint4*>(g_xrh + (size_t)nn * 8)[c];
    uint32_t xv[4] = {xw.x, xw.y, xw.z, xw.w};

    float h[8], r[8];
#pragma unroll
    for (int i = 0; i < 4; i++) {
        __half2 h2 = *reinterpret_cast<__half2*>(&aw[i]);
        float2 f = __half22float2(h2);
        h[2*i]   = f.x * inv;
        h[2*i+1] = f.y * inv;
        __half2 x2 = *reinterpret_cast<__half2*>(&xv[i]);
        float2 fx = __half22float2(x2);
        r[2*i]   = fx.x;
        r[2*i+1] = fx.y;
    }
    h[0] = fmaxf(h[0] + bbA.x + r[0], 0.0f);
    h[1] = fmaxf(h[1] + bbA.y + r[1], 0.0f);
    h[2] = fmaxf(h[2] + bbA.z + r[2], 0.0f);
    h[3] = fmaxf(h[3] + bbA.w + r[3], 0.0f);
    h[4] = fmaxf(h[4] + bbB.x + r[4], 0.0f);
    h[5] = fmaxf(h[5] + bbB.y + r[5], 0.0f);
    h[6] = fmaxf(h[6] + bbB.z + r[6], 0.0f);
    h[7] = fmaxf(h[7] + bbB.w + r[7], 0.0f);

    if (valid) {
        uint32_t hw[4];
#pragma unroll
        for (int i = 0; i < 4; i++) {
            __half2 h2 = __floats2half2_rn(h[2*i], h[2*i+1]);
            hw[i] = *reinterpret_cast<uint32_t*>(&h2);
        }
        reinterpret_cast<uint4*>(g_h1h + (size_t)n * 8)[c] = make_uint4(hw[0], hw[1], hw[2], hw[3]);
        ap[c] = make_uint4(0, 0, 0, 0);       // re-zero agg1 (invariant)
    } else {
#pragma unroll
        for (int o = 0; o < 8; o++) h[o] = 0.0f;
    }

    // ---- readout: reduce over the 16 nodes in this warp, preserving half-id c ----
    int g0 = __shfl_sync(0xffffffffu, g, 0);
    bool uni = __all_sync(0xffffffffu, g == g0);
    int nval = __popc(__ballot_sync(0xffffffffu, valid && c == 0));

    if (uni) {
#pragma unroll
        for (int k = 0; k < 8; k++) {
            float v = h[k];
            v += __shfl_xor_sync(0xffffffffu, v, 16);
            v += __shfl_xor_sync(0xffffffffu, v, 8);
            v += __shfl_xor_sync(0xffffffffu, v, 4);
            v += __shfl_xor_sync(0xffffffffu, v, 2);
            h[k] = v;
        }
        if (lane < 2) {                 // lane 0: c=0 half, lane 1: c=1 half
            float* gp = g_h1acc + (size_t)g0 * HID + lane * 8;
            red_add_v4f(gp + 0, h[0], h[1], h[2], h[3]);
            red_add_v4f(gp + 4, h[4], h[5], h[6], h[7]);
        }
        if (lane == 0 && nval > 0) atomicAdd(&g_gcnt[g0], (float)nval);
    } else if (valid) {
        float* gp = g_h1acc + (size_t)g * HID + c * 8;
        red_add_v4f(gp + 0, h[0], h[1], h[2], h[3]);
        red_add_v4f(gp + 4, h[4], h[5], h[6], h[7]);
        if (c == 0) atomicAdd(&g_gcnt[g], 1.0f);
    }
}

// ---------------- Kernel 5: m2 readout, 2 threads/node; re-zero agg2 + cnt; EARLY trigger ----------------
__global__ void __launch_bounds__(256) kMean2R(const int* __restrict__ batch) {
    int idx = blockIdx.x * blockDim.x + threadIdx.x;
    int n = idx >> 1;
    int c = idx & 1;
    bool valid = n < N_NODESC;
    int nn = valid ? n : (N_NODESC - 1);
    int lane = threadIdx.x & 31;

    int g = __ldg(&batch[nn]);          // input-only prologue

    cudaGridDependencySynchronize();    // agg2/cnt visible
    cudaTriggerProgrammaticLaunchCompletion();   // kFinal may launch now

    float inv = 1.0f / fmaxf(g_cnt[nn], 1.0f);
    uint4* ap = reinterpret_cast<uint4*>(g_agg2h + (size_t)nn * 8);
    uint4 a = ap[c];
    uint32_t aw[4] = {a.x, a.y, a.z, a.w};

    if (valid) {
        ap[c] = make_uint4(0, 0, 0, 0);       // re-zero agg2 (invariant)
        if (c == 0) g_cnt[n] = 0.0f;          // re-zero cnt (invariant; after last read)
    }

    float m[8];
#pragma unroll
    for (int i = 0; i < 4; i++) {
        __half2 h2 = *reinterpret_cast<__half2*>(&aw[i]);
        float2 f = __half22float2(h2);
        m[2*i]   = valid ? f.x * inv : 0.0f;
        m[2*i+1] = valid ? f.y * inv : 0.0f;
    }

    int g0 = __shfl_sync(0xffffffffu, g, 0);
    bool uni = __all_sync(0xffffffffu, g == g0);

    if (uni) {
#pragma unroll
        for (int k = 0; k < 8; k++) {
            float v = m[k];
            v += __shfl_xor_sync(0xffffffffu, v, 16);
            v += __shfl_xor_sync(0xffffffffu, v, 8);
            v += __shfl_xor_sync(0xffffffffu, v, 4);
            v += __shfl_xor_sync(0xffffffffu, v, 2);
            m[k] = v;
        }
        if (lane < 2) {
            float* gp = g_m2acc + (size_t)g0 * HID + lane * 8;
            red_add_v4f(gp + 0, m[0], m[1], m[2], m[3]);
            red_add_v4f(gp + 4, m[4], m[5], m[6], m[7]);
        }
    } else if (valid) {
        float* gp = g_m2acc + (size_t)g * HID + c * 8;
        red_add_v4f(gp + 0, m[0], m[1], m[2], m[3]);
        red_add_v4f(gp + 4, m[4], m[5], m[6], m[7]);
    }
}

// ---------------- Kernel 6: tiny output GEMM; PDL ----------------
__global__ void __launch_bounds__(256) kFinal(const float* __restrict__ w2l,
                                              const float* __restrict__ b2,
                                              const float* __restrict__ w2r,
                                              float* __restrict__ out) {
    int i = blockIdx.x * blockDim.x + threadIdx.x;
    bool act = i < NUM_GRAPHS * OUT_CH;
    int g = i >> 6;
    int o = i & 63;

    float bias = 0.0f;
    float4 wl[4], wr[4];
    if (act) {
        bias = __ldg(&b2[o]);
#pragma unroll
        for (int k = 0; k < 4; k++) {
            wl[k] = __ldg(reinterpret_cast<const float4*>(w2l + o * HID + k * 4));
            wr[k] = __ldg(reinterpret_cast<const float4*>(w2r + o * HID + k * 4));
        }
    }

    cudaGridDependencySynchronize();

    if (!act) return;
    float cnt = g_gcnt[g];
    if (cnt < 0.5f) { out[i] = 0.0f; return; }
    float inv = 1.0f / cnt;

    float sum = bias;
#pragma unroll
    for (int k = 0; k < 4; k++) {
        float4 mm = *reinterpret_cast<const float4*>(&g_m2acc[g * HID + k * 4]);
        float4 hh = *reinterpret_cast<const float4*>(&g_h1acc[g * HID + k * 4]);
        sum += inv * (mm.x * wl[k].x + mm.y * wl[k].y + mm.z * wl[k].z + mm.w * wl[k].w
                    + hh.x * wr[k].x + hh.y * wr[k].y + hh.z * wr[k].z + hh.w * wr[k].w);
    }
    out[i] = sum;
}

// ---------------- launch ----------------
template <typename K, typename... Args>
static void launchPDL(int grid, int block, K kernel, Args... args) {
    cudaLaunchConfig_t cfg = {};
    cfg.gridDim = dim3(grid);
    cfg.blockDim = dim3(block);
    cfg.stream = 0;
    cudaLaunchAttribute attr[1];
    attr[0].id = cudaLaunchAttributeProgrammaticStreamSerialization;
    attr[0].val.programmaticStreamSerializationAllowed = 1;
    cfg.attrs = attr;
    cfg.numAttrs = 1;
    cudaLaunchKernelEx(&cfg, kernel, args...);
}

extern "C" void kernel_launch(void* const* d_in, const int* in_sizes, int n_in,
                              void* d_out, int out_size) {
    const float* x    = (const float*)d_in[0];
    const int*   ei   = (const int*)d_in[1];
    const int*   batch= (const int*)d_in[2];
    const float* w1l  = (const float*)d_in[3];
    const float* b1   = (const float*)d_in[4];
    const float* w1r  = (const float*)d_in[5];
    const float* w2l  = (const float*)d_in[6];
    const float* b2   = (const float*)d_in[7];
    const float* w2r  = (const float*)d_in[8];
    float* out = (float*)d_out;

    __half2* gy;  cudaGetSymbolAddress((void**)&gy,  g_yh);
    __half2* gh1; cudaGetSymbolAddress((void**)&gh1, g_h1h);
    __half2* ga1; cudaGetSymbolAddress((void**)&ga1, g_agg1h);
    __half2* ga2; cudaGetSymbolAddress((void**)&ga2, g_agg2h);

    const int TB = 256;
    int nodeBlocks  = (N_NODESC + TB - 1) / TB;
    int node2Blocks = (N_NODESC * 2 + TB - 1) / TB;    // 2 threads/node
    int scatBlocks  = (N_EDGESC / 2 + TB - 1) / TB;    // 4 edges / thread-pair

    kPre<<<nodeBlocks, TB>>>(x, w1l, w1r);
    launchPDL(scatBlocks, TB, kScatterH<1>, ei, (const __half2*)gy, ga1);
    launchPDL(node2Blocks, TB, kLayer1R, b1, batch);
    launchPDL(scatBlocks, TB, kScatterH<0>, ei, (const __half2*)gh1, ga2);
    launchPDL(node2Blocks, TB, kMean2R, batch);
    launchPDL((NUM_GRAPHS * OUT_CH + TB - 1) / TB, TB, kFinal, w2l, b2, w2r, out);
}